// round 1
// baseline (speedup 1.0000x reference)
#include <cuda_runtime.h>
#include <cuda_bf16.h>
#include <cstdint>
#include <math_constants.h>

// ---------------------------------------------------------------------------
// GAT, 3 layers, N=4096, F_IN=256, HID=256, OUT=128, HEADS=4.
// Strategy: build CSR from dense adjacency once per launch, then per layer:
//   1. Wh = A @ W (per-head concat)  -- tiled fp32 GEMM
//   2. s/t = Wh . a_src / a_dst      -- warp-per-(node,head) dot
//   3. sparse masked softmax + neighbor aggregation (online softmax, chunked)
// ---------------------------------------------------------------------------

#define GN    4096
#define HEADS 4
#define MAX_E (1 << 19)   // ~172K edges expected; huge safety margin

__device__ float g_Wh[GN * 512];     // projected features (max K = 4*128)
__device__ float g_h [GN * 256];     // inter-layer activations
__device__ float g_s [HEADS * GN];
__device__ float g_t [HEADS * GN];
__device__ int   g_row_ptr[GN + 1];
__device__ int   g_cnt[GN];
__device__ int   g_col_idx[MAX_E];
__device__ int   g_byte_mode;        // 1: adj is 1 byte/elem, 0: 4 bytes/elem

// ---------------------------------------------------------------------------
// Adjacency dtype detection. adj is jnp bool; harness may hand us uint8,
// int32 or float32. Values are only 0/1 (or 0.0f/1.0f) and adj[0][0] is a
// guaranteed self-loop.
//   uint8  : nonzero bytes at offsets %4==0 AND %4!=0
//   int32  : nonzero only at offsets %4==0 (LSB of value 1)
//   float32: 1.0f = 00 00 80 3F -> nonzero only at offsets %4!=0
// A single nonzero-word test handles int32 and float32 identically, so we
// only need byte-mode vs word-mode.
// ---------------------------------------------------------------------------
__global__ void detect_kernel(const unsigned char* __restrict__ adj) {
    __shared__ int s_mis, s_b0;
    if (threadIdx.x == 0) { s_mis = 0; s_b0 = 0; }
    __syncthreads();
    int mis = 0, b0 = 0;
    for (int off = threadIdx.x; off < (1 << 20); off += blockDim.x) {
        unsigned char v = adj[off];
        if (v) { if (off & 3) mis++; else b0++; }
    }
    if (mis) atomicAdd(&s_mis, mis);
    if (b0)  atomicAdd(&s_b0, b0);
    __syncthreads();
    if (threadIdx.x == 0) g_byte_mode = (s_mis > 0 && s_b0 > 0) ? 1 : 0;
}

__device__ __forceinline__ bool adj_set(const void* adj, int r, int c, int bm) {
    size_t idx = (size_t)r * GN + c;
    if (bm) return ((const unsigned char*)adj)[idx] != 0;
    return ((const unsigned int*)adj)[idx] != 0u;
}

// one block per row: count neighbors
__global__ void csr_count(const void* __restrict__ adj) {
    int r = blockIdx.x;
    int bm = g_byte_mode;
    int cnt = 0;
    for (int c = threadIdx.x; c < GN; c += 128)
        cnt += adj_set(adj, r, c, bm) ? 1 : 0;
    #pragma unroll
    for (int o = 16; o; o >>= 1) cnt += __shfl_xor_sync(0xffffffffu, cnt, o);
    __shared__ int sh[4];
    if ((threadIdx.x & 31) == 0) sh[threadIdx.x >> 5] = cnt;
    __syncthreads();
    if (threadIdx.x == 0) g_cnt[r] = sh[0] + sh[1] + sh[2] + sh[3];
}

// single-block scan of 4096 counts -> row_ptr
__global__ void csr_scan() {
    __shared__ int sh[1024];
    int t = threadIdx.x;
    int v0 = g_cnt[4 * t + 0], v1 = g_cnt[4 * t + 1];
    int v2 = g_cnt[4 * t + 2], v3 = g_cnt[4 * t + 3];
    int sum = v0 + v1 + v2 + v3;
    sh[t] = sum;
    __syncthreads();
    for (int off = 1; off < 1024; off <<= 1) {
        int x = (t >= off) ? sh[t - off] : 0;
        __syncthreads();
        sh[t] += x;
        __syncthreads();
    }
    int excl = sh[t] - sum;
    g_row_ptr[4 * t + 0] = excl;
    g_row_ptr[4 * t + 1] = excl + v0;
    g_row_ptr[4 * t + 2] = excl + v0 + v1;
    g_row_ptr[4 * t + 3] = excl + v0 + v1 + v2;
    if (t == 1023) g_row_ptr[GN] = excl + sum;
}

// warp per row, ballot-ordered (deterministic column order, no atomics)
__global__ void csr_fill(const void* __restrict__ adj) {
    int warp = (blockIdx.x * blockDim.x + threadIdx.x) >> 5;
    if (warp >= GN) return;
    int lane = threadIdx.x & 31;
    int bm = g_byte_mode;
    int base = g_row_ptr[warp];
    for (int ch = 0; ch < GN / 32; ch++) {
        int c = ch * 32 + lane;
        bool st = adj_set(adj, warp, c, bm);
        unsigned mask = __ballot_sync(0xffffffffu, st);
        if (st) {
            int pos = base + __popc(mask & ((1u << lane) - 1u));
            if (pos < MAX_E) g_col_idx[pos] = c;
        }
        base += __popc(mask);
    }
}

// ---------------------------------------------------------------------------
// Projection GEMM: C[n, h*D+d] = sum_f A[n,f] * W[(h*F+f)*D + d]
// 64x64 tile, BK=16, 256 threads, 4x4 micro-tile per thread.
// BN=64 always lies within one head (D is 64 or 128).
// ---------------------------------------------------------------------------
__global__ __launch_bounds__(256) void gemm_proj(
    const float* __restrict__ A, const float* __restrict__ W,
    float* __restrict__ C, int F, int D)
{
    const int BK = 16;
    __shared__ float As[BK][64 + 4];
    __shared__ float Bs[BK][64 + 4];
    int K  = HEADS * D;
    int c0 = blockIdx.x * 64;
    int n0 = blockIdx.y * 64;
    int h  = c0 / D;
    int d0 = c0 % D;
    int tid = threadIdx.x;
    int tx = tid & 15, ty = tid >> 4;

    const float* Wbase = W + (size_t)h * F * D + d0;
    float acc[4][4] = {};

    int am = tid >> 2, ak = (tid & 3) * 4;        // A-tile load mapping
    int bk = tid >> 4, bc = (tid & 15) * 4;       // B-tile load mapping

    for (int k0 = 0; k0 < F; k0 += BK) {
        float4 av = *(const float4*)&A[(size_t)(n0 + am) * F + k0 + ak];
        As[ak + 0][am] = av.x; As[ak + 1][am] = av.y;
        As[ak + 2][am] = av.z; As[ak + 3][am] = av.w;
        float4 bv = *(const float4*)&Wbase[(size_t)(k0 + bk) * D + bc];
        Bs[bk][bc + 0] = bv.x; Bs[bk][bc + 1] = bv.y;
        Bs[bk][bc + 2] = bv.z; Bs[bk][bc + 3] = bv.w;
        __syncthreads();
        #pragma unroll
        for (int kk = 0; kk < BK; kk++) {
            float4 a4 = *(const float4*)&As[kk][ty * 4];
            float4 b4 = *(const float4*)&Bs[kk][tx * 4];
            float a[4] = {a4.x, a4.y, a4.z, a4.w};
            float b[4] = {b4.x, b4.y, b4.z, b4.w};
            #pragma unroll
            for (int r = 0; r < 4; r++)
                #pragma unroll
                for (int c = 0; c < 4; c++)
                    acc[r][c] += a[r] * b[c];
        }
        __syncthreads();
    }
    #pragma unroll
    for (int r = 0; r < 4; r++) {
        float4 o = {acc[r][0], acc[r][1], acc[r][2], acc[r][3]};
        *(float4*)&C[(size_t)(n0 + ty * 4 + r) * K + c0 + tx * 4] = o;
    }
}

// ---------------------------------------------------------------------------
// Attention scores: s[h*N+n] = Wh[n, hD:..] . a_src[h], same for t.
// One warp per (n, h); reuse the Wh load for both dots.
// ---------------------------------------------------------------------------
__global__ __launch_bounds__(256) void score_kernel(
    const float* __restrict__ Wh, const float* __restrict__ a_src,
    const float* __restrict__ a_dst, float* __restrict__ s,
    float* __restrict__ t, int D)
{
    int warp = (blockIdx.x * blockDim.x + threadIdx.x) >> 5;
    if (warp >= GN * HEADS) return;
    int lane = threadIdx.x & 31;
    int n = warp >> 2;
    int h = warp & 3;
    int K = HEADS * D;
    float ss = 0.f, tt = 0.f;
    for (int d = lane; d < D; d += 32) {
        float v = Wh[(size_t)n * K + h * D + d];
        ss += v * a_src[h * D + d];
        tt += v * a_dst[h * D + d];
    }
    #pragma unroll
    for (int o = 16; o; o >>= 1) {
        ss += __shfl_xor_sync(0xffffffffu, ss, o);
        tt += __shfl_xor_sync(0xffffffffu, tt, o);
    }
    if (lane == 0) { s[h * GN + n] = ss; t[h * GN + n] = tt; }
}

// ---------------------------------------------------------------------------
// Sparse masked softmax + aggregation.  Block per destination node.
// Online softmax over neighbor chunks of 128.  Thread c owns output
// channel(s) c (and c+256 when K=512).  meanMode: layer-2 head-mean, no ELU.
// ---------------------------------------------------------------------------
__global__ __launch_bounds__(256) void agg_kernel(
    const float* __restrict__ Wh, const float* __restrict__ s,
    const float* __restrict__ t,  float* __restrict__ out,
    int D, int meanMode)
{
    const int NT = 256, CH = 128;
    int K = HEADS * D;
    int CPT = K >> 8;              // 1 (D=64) or 2 (D=128)
    __shared__ int   sidx[CH];
    __shared__ float sw[HEADS][CH];
    __shared__ float sm[HEADS], sz[HEADS], sscale[HEADS], ssrc[HEADS];
    __shared__ float buf[512];

    int i   = blockIdx.x;
    int tid = threadIdx.x;
    if (tid < HEADS) {
        ssrc[tid] = s[tid * GN + i];
        sm[tid] = -CUDART_INF_F;
        sz[tid] = 0.f;
    }
    int start = g_row_ptr[i], end = g_row_ptr[i + 1];
    int h0 = tid / D;
    int h1 = (tid + NT) / D;
    float acc0 = 0.f, acc1 = 0.f;
    __syncthreads();

    for (int base = start; base < end; base += CH) {
        int cnt = min(CH, end - base);
        if (tid < cnt) sidx[tid] = g_col_idx[base + tid];
        __syncthreads();
        if (tid < cnt) {
            int j = sidx[tid];
            #pragma unroll
            for (int h = 0; h < HEADS; h++) {
                float z = ssrc[h] + t[h * GN + j];
                sw[h][tid] = (z > 0.f) ? z : 0.2f * z;     // leaky relu
            }
        }
        __syncthreads();
        int wid = tid >> 5, lane = tid & 31;
        if (wid < HEADS) {
            int h = wid;
            float mx = -CUDART_INF_F;
            for (int k = lane; k < cnt; k += 32) mx = fmaxf(mx, sw[h][k]);
            #pragma unroll
            for (int o = 16; o; o >>= 1) mx = fmaxf(mx, __shfl_xor_sync(0xffffffffu, mx, o));
            float oldm = sm[h];
            float newm = fmaxf(oldm, mx);
            float sc = (oldm == -CUDART_INF_F) ? 0.f : __expf(oldm - newm);
            float lz = 0.f;
            for (int k = lane; k < cnt; k += 32) {
                float w = __expf(sw[h][k] - newm);
                sw[h][k] = w;
                lz += w;
            }
            #pragma unroll
            for (int o = 16; o; o >>= 1) lz += __shfl_xor_sync(0xffffffffu, lz, o);
            if (lane == 0) {
                sm[h] = newm;
                sz[h] = sz[h] * sc + lz;
                sscale[h] = sc;
            }
        }
        __syncthreads();
        acc0 *= sscale[h0];
        if (CPT == 2) acc1 *= sscale[h1];
        for (int k = 0; k < cnt; k++) {
            const float* wr = Wh + (size_t)sidx[k] * K;
            acc0 += sw[h0][k] * wr[tid];
            if (CPT == 2) acc1 += sw[h1][k] * wr[tid + NT];
        }
        __syncthreads();
    }

    if (!meanMode) {
        float v = acc0 / sz[h0];
        out[(size_t)i * K + tid] = (v > 0.f) ? v : (__expf(v) - 1.f);  // ELU
    } else {
        buf[tid]      = acc0 / sz[h0];
        buf[tid + NT] = acc1 / sz[h1];
        __syncthreads();
        if (tid < D) {
            out[(size_t)i * D + tid] = 0.25f *
                (buf[tid] + buf[D + tid] + buf[2 * D + tid] + buf[3 * D + tid]);
        }
    }
}

// ---------------------------------------------------------------------------
extern "C" void kernel_launch(void* const* d_in, const int* in_sizes, int n_in,
                              void* d_out, int out_size)
{
    const float* x   = (const float*)d_in[0];
    const void*  adj =               d_in[1];
    const float* W0  = (const float*)d_in[2];
    const float* a0s = (const float*)d_in[3];
    const float* a0d = (const float*)d_in[4];
    const float* W1  = (const float*)d_in[5];
    const float* a1s = (const float*)d_in[6];
    const float* a1d = (const float*)d_in[7];
    const float* W2  = (const float*)d_in[8];
    const float* a2s = (const float*)d_in[9];
    const float* a2d = (const float*)d_in[10];
    float* out = (float*)d_out;

    float *pWh, *ph, *ps, *pt;
    cudaGetSymbolAddress((void**)&pWh, g_Wh);
    cudaGetSymbolAddress((void**)&ph,  g_h);
    cudaGetSymbolAddress((void**)&ps,  g_s);
    cudaGetSymbolAddress((void**)&pt,  g_t);

    // CSR build (once; same graph for all 3 layers)
    detect_kernel<<<1, 1024>>>((const unsigned char*)adj);
    csr_count<<<GN, 128>>>(adj);
    csr_scan<<<1, 1024>>>();
    csr_fill<<<GN / 8, 256>>>(adj);

    dim3 g64(4, 64);   // K=256
    dim3 g128(8, 64);  // K=512
    int score_blocks = (GN * HEADS * 32) / 256;

    // Layer 0: x[4096,256] -> h[4096,256]
    gemm_proj<<<g64, 256>>>(x, W0, pWh, 256, 64);
    score_kernel<<<score_blocks, 256>>>(pWh, a0s, a0d, ps, pt, 64);
    agg_kernel<<<GN, 256>>>(pWh, ps, pt, ph, 64, 0);

    // Layer 1: h -> h
    gemm_proj<<<g64, 256>>>(ph, W1, pWh, 256, 64);
    score_kernel<<<score_blocks, 256>>>(pWh, a1s, a1d, ps, pt, 64);
    agg_kernel<<<GN, 256>>>(pWh, ps, pt, ph, 64, 0);

    // Layer 2: h -> out[4096,128] (head mean, no ELU)
    gemm_proj<<<g128, 256>>>(ph, W2, pWh, 256, 128);
    score_kernel<<<score_blocks, 256>>>(pWh, a2s, a2d, ps, pt, 128);
    agg_kernel<<<GN, 256>>>(pWh, ps, pt, out, 128, 1);
}

// round 2
// speedup vs baseline: 1.3032x; 1.3032x over previous
#include <cuda_runtime.h>
#include <cuda_fp16.h>
#include <cstdint>
#include <math_constants.h>

// ---------------------------------------------------------------------------
// GAT, 3 layers, N=4096, F_IN=256, HID=256, OUT=128, HEADS=4.
// Round 2: one-pass vectorized padded CSR; fp16 Wh copy for aggregation
// (fp32 accumulate); single-chunk softmax (degree <= 128).
// ---------------------------------------------------------------------------

#define GN    4096
#define HEADS 4
#define PAD   128          // max supported degree (expected max ~75)

__device__ float  g_Wh [GN * 512];    // fp32 projected features (for scores)
__device__ __half g_WhH[GN * 512];    // fp16 copy (for aggregation)
__device__ float  g_h  [GN * 256];    // inter-layer activations
__device__ float  g_s  [HEADS * GN];
__device__ float  g_t  [HEADS * GN];
__device__ int    g_cnt[GN];
__device__ int    g_col_idx[GN * PAD];
__device__ int    g_byte_mode;        // 1: adj is 1 byte/elem, 0: 4 bytes/elem

// ---------------------------------------------------------------------------
// Adjacency dtype detection (cheap: 64KB scan, 1 block).
//   uint8  : nonzero bytes at offsets %4==0 AND %4!=0
//   int32  : nonzero only at %4==0
//   float32: 1.0f = 00 00 80 3F -> nonzero only at %4!=0
// Word-mode readers (v != 0) handle int32 and float32 identically.
// ---------------------------------------------------------------------------
__global__ void detect_kernel(const unsigned char* __restrict__ adj) {
    __shared__ int s_mis, s_b0;
    if (threadIdx.x == 0) { s_mis = 0; s_b0 = 0; }
    __syncthreads();
    int mis = 0, b0 = 0;
    for (int off = threadIdx.x; off < (1 << 16); off += blockDim.x) {
        unsigned char v = adj[off];
        if (v) { if (off & 3) mis++; else b0++; }
    }
    if (mis) atomicAdd(&s_mis, mis);
    if (b0)  atomicAdd(&s_b0, b0);
    __syncthreads();
    if (threadIdx.x == 0) g_byte_mode = (s_mis > 0 && s_b0 > 0) ? 1 : 0;
}

// ---------------------------------------------------------------------------
// One-pass padded CSR build: warp per row, uint4 loads, ballot-free
// shfl-scan ordering (deterministic ascending column order, no atomics).
// ---------------------------------------------------------------------------
__device__ __forceinline__ int warp_excl_scan(int v, int lane, int& tot) {
    int p = v;
    #pragma unroll
    for (int o = 1; o < 32; o <<= 1) {
        int x = __shfl_up_sync(0xffffffffu, p, o);
        if (lane >= o) p += x;
    }
    tot = __shfl_sync(0xffffffffu, p, 31);
    return p - v;
}

__global__ __launch_bounds__(256) void csr_build(const void* __restrict__ adj) {
    int warp = (blockIdx.x * blockDim.x + threadIdx.x) >> 5;
    if (warp >= GN) return;
    int lane = threadIdx.x & 31;
    int r    = warp;
    int base = r * PAD;
    int total = 0;
    int lim = base + PAD;

    if (!g_byte_mode) {
        // 4096 words/row = 32 iters of 32 lanes x uint4
        const uint4* p = (const uint4*)adj + (size_t)r * 1024;
        for (int it = 0; it < 32; it++) {
            uint4 v = p[it * 32 + lane];
            int b0 = (v.x != 0u), b1 = (v.y != 0u), b2 = (v.z != 0u), b3 = (v.w != 0u);
            int own = b0 + b1 + b2 + b3;
            int tot;
            int excl = warp_excl_scan(own, lane, tot);
            int pos = base + total + excl;
            int c0 = it * 128 + lane * 4;
            if (b0) { if (pos < lim) g_col_idx[pos] = c0 + 0; pos++; }
            if (b1) { if (pos < lim) g_col_idx[pos] = c0 + 1; pos++; }
            if (b2) { if (pos < lim) g_col_idx[pos] = c0 + 2; pos++; }
            if (b3) { if (pos < lim) g_col_idx[pos] = c0 + 3; pos++; }
            total += tot;
        }
    } else {
        // 4096 bytes/row = 8 iters of 32 lanes x 16 bytes
        const uint4* p = (const uint4*)adj + (size_t)r * 256;
        for (int it = 0; it < 8; it++) {
            uint4 v = p[it * 32 + lane];
            unsigned w[4] = {v.x, v.y, v.z, v.w};
            int own = 0;
            #pragma unroll
            for (int q = 0; q < 4; q++)
                #pragma unroll
                for (int b = 0; b < 4; b++)
                    own += ((w[q] >> (8 * b)) & 0xFFu) ? 1 : 0;
            int tot;
            int excl = warp_excl_scan(own, lane, tot);
            int pos = base + total + excl;
            int c0 = it * 512 + lane * 16;
            #pragma unroll
            for (int q = 0; q < 4; q++)
                #pragma unroll
                for (int b = 0; b < 4; b++)
                    if ((w[q] >> (8 * b)) & 0xFFu) {
                        if (pos < lim) g_col_idx[pos] = c0 + q * 4 + b;
                        pos++;
                    }
            total += tot;
        }
    }
    if (lane == 0) g_cnt[r] = (total < PAD) ? total : PAD;
}

// ---------------------------------------------------------------------------
// Projection GEMM: C[n, h*D+d] = sum_f A[n,f] * W[(h*F+f)*D + d]
// 64x64 tile, BK=16, 256 threads, 4x4 micro-tile. Also emits fp16 copy.
// ---------------------------------------------------------------------------
__global__ __launch_bounds__(256) void gemm_proj(
    const float* __restrict__ A, const float* __restrict__ W,
    float* __restrict__ C, __half* __restrict__ Ch, int F, int D)
{
    const int BK = 16;
    __shared__ float As[BK][64 + 4];
    __shared__ float Bs[BK][64 + 4];
    int K  = HEADS * D;
    int c0 = blockIdx.x * 64;
    int n0 = blockIdx.y * 64;
    int h  = c0 / D;
    int d0 = c0 % D;
    int tid = threadIdx.x;
    int tx = tid & 15, ty = tid >> 4;

    const float* Wbase = W + (size_t)h * F * D + d0;
    float acc[4][4] = {};

    int am = tid >> 2, ak = (tid & 3) * 4;
    int bk = tid >> 4, bc = (tid & 15) * 4;

    for (int k0 = 0; k0 < F; k0 += BK) {
        float4 av = *(const float4*)&A[(size_t)(n0 + am) * F + k0 + ak];
        As[ak + 0][am] = av.x; As[ak + 1][am] = av.y;
        As[ak + 2][am] = av.z; As[ak + 3][am] = av.w;
        float4 bv = *(const float4*)&Wbase[(size_t)(k0 + bk) * D + bc];
        Bs[bk][bc + 0] = bv.x; Bs[bk][bc + 1] = bv.y;
        Bs[bk][bc + 2] = bv.z; Bs[bk][bc + 3] = bv.w;
        __syncthreads();
        #pragma unroll
        for (int kk = 0; kk < BK; kk++) {
            float4 a4 = *(const float4*)&As[kk][ty * 4];
            float4 b4 = *(const float4*)&Bs[kk][tx * 4];
            float a[4] = {a4.x, a4.y, a4.z, a4.w};
            float b[4] = {b4.x, b4.y, b4.z, b4.w};
            #pragma unroll
            for (int r = 0; r < 4; r++)
                #pragma unroll
                for (int c = 0; c < 4; c++)
                    acc[r][c] += a[r] * b[c];
        }
        __syncthreads();
    }
    #pragma unroll
    for (int r = 0; r < 4; r++) {
        size_t idx = (size_t)(n0 + ty * 4 + r) * K + c0 + tx * 4;
        float4 o = {acc[r][0], acc[r][1], acc[r][2], acc[r][3]};
        *(float4*)&C[idx] = o;
        __half2 h01 = __floats2half2_rn(o.x, o.y);
        __half2 h23 = __floats2half2_rn(o.z, o.w);
        *(__half2*)&Ch[idx]     = h01;
        *(__half2*)&Ch[idx + 2] = h23;
    }
}

// ---------------------------------------------------------------------------
// Attention scores (fp32): warp per (node, head).
// ---------------------------------------------------------------------------
__global__ __launch_bounds__(256) void score_kernel(
    const float* __restrict__ Wh, const float* __restrict__ a_src,
    const float* __restrict__ a_dst, float* __restrict__ s,
    float* __restrict__ t, int D)
{
    int warp = (blockIdx.x * blockDim.x + threadIdx.x) >> 5;
    if (warp >= GN * HEADS) return;
    int lane = threadIdx.x & 31;
    int n = warp >> 2;
    int h = warp & 3;
    int K = HEADS * D;
    float ss = 0.f, tt = 0.f;
    for (int d = lane; d < D; d += 32) {
        float v = Wh[(size_t)n * K + h * D + d];
        ss += v * a_src[h * D + d];
        tt += v * a_dst[h * D + d];
    }
    #pragma unroll
    for (int o = 16; o; o >>= 1) {
        ss += __shfl_xor_sync(0xffffffffu, ss, o);
        tt += __shfl_xor_sync(0xffffffffu, tt, o);
    }
    if (lane == 0) { s[h * GN + n] = ss; t[h * GN + n] = tt; }
}

// ---------------------------------------------------------------------------
// Sparse softmax + aggregation. Block per destination node, single chunk
// (degree <= PAD). fp16 Wh reads (half2), fp32 accumulate.
// Thread layout: CP = K/2 channel-pairs, G = 256/CP neighbor groups.
// ---------------------------------------------------------------------------
__global__ __launch_bounds__(256) void agg_kernel(
    const __half* __restrict__ WhH, const float* __restrict__ s,
    const float* __restrict__ t,  float* __restrict__ out,
    int D, int meanMode)
{
    int K  = HEADS * D;
    int CP = K >> 1;          // 128 (K=256) or 256 (K=512)
    int G  = 256 / CP;        // 2 or 1
    __shared__ int   sidx[PAD];
    __shared__ float sw[HEADS][PAD];
    __shared__ float sz[HEADS], ssrc[HEADS];
    __shared__ float buf[512];

    int i   = blockIdx.x;
    int tid = threadIdx.x;
    int cp  = tid % CP;
    int g   = tid / CP;
    int h   = (2 * cp) / D;

    if (tid < HEADS) ssrc[tid] = s[tid * GN + i];
    int cnt = g_cnt[i];
    if (tid < cnt) sidx[tid] = g_col_idx[i * PAD + tid];
    __syncthreads();

    if (tid < cnt) {
        int j = sidx[tid];
        #pragma unroll
        for (int hh = 0; hh < HEADS; hh++) {
            float z = ssrc[hh] + t[hh * GN + j];
            sw[hh][tid] = (z > 0.f) ? z : 0.2f * z;     // leaky relu
        }
    }
    __syncthreads();

    {   // per-head softmax: warp w handles head w
        int wid = tid >> 5, lane = tid & 31;
        if (wid < HEADS) {
            int hh = wid;
            float mx = -CUDART_INF_F;
            for (int k = lane; k < cnt; k += 32) mx = fmaxf(mx, sw[hh][k]);
            #pragma unroll
            for (int o = 16; o; o >>= 1)
                mx = fmaxf(mx, __shfl_xor_sync(0xffffffffu, mx, o));
            float lz = 0.f;
            for (int k = lane; k < cnt; k += 32) {
                float w = __expf(sw[hh][k] - mx);
                sw[hh][k] = w;
                lz += w;
            }
            #pragma unroll
            for (int o = 16; o; o >>= 1) lz += __shfl_xor_sync(0xffffffffu, lz, o);
            if (lane == 0) sz[hh] = lz;
        }
    }
    __syncthreads();

    // aggregation: group g handles neighbors k = g, g+G, ...
    float ax = 0.f, ay = 0.f;
    const float* swh = sw[h];
    #pragma unroll 4
    for (int k = g; k < cnt; k += G) {
        float w = swh[k];
        float2 v = __half22float2(*(const __half2*)&WhH[(size_t)sidx[k] * K + 2 * cp]);
        ax += w * v.x;
        ay += w * v.y;
    }

    if (G == 2) {
        // combine the two neighbor groups via smem
        buf[2 * tid]     = ax;
        buf[2 * tid + 1] = ay;
        __syncthreads();
        if (tid < CP) {
            ax = buf[2 * tid]     + buf[2 * (tid + CP)];
            ay = buf[2 * tid + 1] + buf[2 * (tid + CP) + 1];
            float inv = 1.f / sz[h];
            float vx = ax * inv, vy = ay * inv;
            vx = (vx > 0.f) ? vx : (__expf(vx) - 1.f);   // ELU (concat layers)
            vy = (vy > 0.f) ? vy : (__expf(vy) - 1.f);
            float2 o = {vx, vy};
            *(float2*)&out[(size_t)i * K + 2 * cp] = o;
        }
    } else {
        // meanMode: K=512, mean over heads, no ELU
        float inv = 1.f / sz[h];
        buf[2 * cp]     = ax * inv;
        buf[2 * cp + 1] = ay * inv;
        __syncthreads();
        if (tid < D) {
            out[(size_t)i * D + tid] = 0.25f *
                (buf[tid] + buf[D + tid] + buf[2 * D + tid] + buf[3 * D + tid]);
        }
    }
}

// ---------------------------------------------------------------------------
extern "C" void kernel_launch(void* const* d_in, const int* in_sizes, int n_in,
                              void* d_out, int out_size)
{
    const float* x   = (const float*)d_in[0];
    const void*  adj =               d_in[1];
    const float* W0  = (const float*)d_in[2];
    const float* a0s = (const float*)d_in[3];
    const float* a0d = (const float*)d_in[4];
    const float* W1  = (const float*)d_in[5];
    const float* a1s = (const float*)d_in[6];
    const float* a1d = (const float*)d_in[7];
    const float* W2  = (const float*)d_in[8];
    const float* a2s = (const float*)d_in[9];
    const float* a2d = (const float*)d_in[10];
    float* out = (float*)d_out;

    float  *pWh, *ph, *ps, *pt;
    __half *pWhH;
    cudaGetSymbolAddress((void**)&pWh,  g_Wh);
    cudaGetSymbolAddress((void**)&pWhH, g_WhH);
    cudaGetSymbolAddress((void**)&ph,   g_h);
    cudaGetSymbolAddress((void**)&ps,   g_s);
    cudaGetSymbolAddress((void**)&pt,   g_t);

    // CSR build (once; same graph for all 3 layers)
    detect_kernel<<<1, 256>>>((const unsigned char*)adj);
    csr_build<<<GN / 8, 256>>>(adj);

    dim3 g64(4, 64);   // K=256
    dim3 g128(8, 64);  // K=512
    int score_blocks = (GN * HEADS * 32) / 256;

    // Layer 0: x[4096,256] -> h[4096,256]
    gemm_proj<<<g64, 256>>>(x, W0, pWh, pWhH, 256, 64);
    score_kernel<<<score_blocks, 256>>>(pWh, a0s, a0d, ps, pt, 64);
    agg_kernel<<<GN, 256>>>(pWhH, ps, pt, ph, 64, 0);

    // Layer 1: h -> h
    gemm_proj<<<g64, 256>>>(ph, W1, pWh, pWhH, 256, 64);
    score_kernel<<<score_blocks, 256>>>(pWh, a1s, a1d, ps, pt, 64);
    agg_kernel<<<GN, 256>>>(pWhH, ps, pt, ph, 64, 0);

    // Layer 2: h -> out[4096,128] (head mean, no ELU)
    gemm_proj<<<g128, 256>>>(ph, W2, pWh, pWhH, 256, 128);
    score_kernel<<<score_blocks, 256>>>(pWh, a2s, a2d, ps, pt, 128);
    agg_kernel<<<GN, 256>>>(pWhH, ps, pt, out, 128, 1);
}

// round 3
// speedup vs baseline: 2.0398x; 1.5652x over previous
#include <cuda_runtime.h>
#include <cuda_fp16.h>
#include <cstdint>
#include <math_constants.h>

// ---------------------------------------------------------------------------
// GAT, 3 layers, N=4096, F_IN=256, HID=256, OUT=128, HEADS=4.
// Round 3: fp16 tensor-core GEMM (mma.sync m16n8k16, fp32 accum), merged
// per-head weights, fp16 everywhere except scores/softmax/accumulators.
// ---------------------------------------------------------------------------

#define GN    4096
#define HEADS 4
#define PAD   128

__device__ __half g_xh [GN * 256];    // fp16 input features
__device__ __half g_Wt [256 * 512];   // fp16 merged weight [F, H*D] (reused)
__device__ __half g_WhH[GN * 512];    // fp16 projected features
__device__ __half g_hH [GN * 256];    // fp16 inter-layer activations
__device__ float  g_s  [HEADS * GN];
__device__ float  g_t  [HEADS * GN];
__device__ int    g_cnt[GN];
__device__ int    g_col_idx[GN * PAD];
__device__ int    g_byte_mode;

// ---------------------------------------------------------------------------
// Adjacency dtype detection (64KB scan).
// ---------------------------------------------------------------------------
__global__ void detect_kernel(const unsigned char* __restrict__ adj) {
    __shared__ int s_mis, s_b0;
    if (threadIdx.x == 0) { s_mis = 0; s_b0 = 0; }
    __syncthreads();
    int mis = 0, b0 = 0;
    for (int off = threadIdx.x; off < (1 << 16); off += blockDim.x) {
        unsigned char v = adj[off];
        if (v) { if (off & 3) mis++; else b0++; }
    }
    if (mis) atomicAdd(&s_mis, mis);
    if (b0)  atomicAdd(&s_b0, b0);
    __syncthreads();
    if (threadIdx.x == 0) g_byte_mode = (s_mis > 0 && s_b0 > 0) ? 1 : 0;
}

// ---------------------------------------------------------------------------
// One-pass padded CSR build (warp/row, uint4 loads, shfl-scan ordering).
// ---------------------------------------------------------------------------
__device__ __forceinline__ int warp_excl_scan(int v, int lane, int& tot) {
    int p = v;
    #pragma unroll
    for (int o = 1; o < 32; o <<= 1) {
        int x = __shfl_up_sync(0xffffffffu, p, o);
        if (lane >= o) p += x;
    }
    tot = __shfl_sync(0xffffffffu, p, 31);
    return p - v;
}

__global__ __launch_bounds__(256) void csr_build(const void* __restrict__ adj) {
    int warp = (blockIdx.x * blockDim.x + threadIdx.x) >> 5;
    if (warp >= GN) return;
    int lane = threadIdx.x & 31;
    int r    = warp;
    int base = r * PAD;
    int total = 0;
    int lim = base + PAD;

    if (!g_byte_mode) {
        const uint4* p = (const uint4*)adj + (size_t)r * 1024;
        for (int it = 0; it < 32; it++) {
            uint4 v = p[it * 32 + lane];
            int b0 = (v.x != 0u), b1 = (v.y != 0u), b2 = (v.z != 0u), b3 = (v.w != 0u);
            int own = b0 + b1 + b2 + b3;
            int tot;
            int excl = warp_excl_scan(own, lane, tot);
            int pos = base + total + excl;
            int c0 = it * 128 + lane * 4;
            if (b0) { if (pos < lim) g_col_idx[pos] = c0 + 0; pos++; }
            if (b1) { if (pos < lim) g_col_idx[pos] = c0 + 1; pos++; }
            if (b2) { if (pos < lim) g_col_idx[pos] = c0 + 2; pos++; }
            if (b3) { if (pos < lim) g_col_idx[pos] = c0 + 3; pos++; }
            total += tot;
        }
    } else {
        const uint4* p = (const uint4*)adj + (size_t)r * 256;
        for (int it = 0; it < 8; it++) {
            uint4 v = p[it * 32 + lane];
            unsigned w[4] = {v.x, v.y, v.z, v.w};
            int own = 0;
            #pragma unroll
            for (int q = 0; q < 4; q++)
                #pragma unroll
                for (int b = 0; b < 4; b++)
                    own += ((w[q] >> (8 * b)) & 0xFFu) ? 1 : 0;
            int tot;
            int excl = warp_excl_scan(own, lane, tot);
            int pos = base + total + excl;
            int c0 = it * 512 + lane * 16;
            #pragma unroll
            for (int q = 0; q < 4; q++)
                #pragma unroll
                for (int b = 0; b < 4; b++)
                    if ((w[q] >> (8 * b)) & 0xFFu) {
                        if (pos < lim) g_col_idx[pos] = c0 + q * 4 + b;
                        pos++;
                    }
            total += tot;
        }
    }
    if (lane == 0) g_cnt[r] = (total < PAD) ? total : PAD;
}

// ---------------------------------------------------------------------------
// Converters.
// ---------------------------------------------------------------------------
__global__ void conv_x(const float* __restrict__ x, __half* __restrict__ xh, int n4) {
    int idx = blockIdx.x * 256 + threadIdx.x;
    if (idx >= n4) return;
    float4 v = ((const float4*)x)[idx];
    ((__half2*)xh)[2 * idx]     = __floats2half2_rn(v.x, v.y);
    ((__half2*)xh)[2 * idx + 1] = __floats2half2_rn(v.z, v.w);
}

// W [H][F][D] fp32  ->  Wt [F][H*D] fp16
__global__ void conv_w(const float* __restrict__ W, __half* __restrict__ Wt,
                       int F, int D) {
    int idx = blockIdx.x * 256 + threadIdx.x;
    int total = HEADS * F * D;
    if (idx >= total) return;
    int h = idx / (F * D);
    int rem = idx % (F * D);
    int f = rem / D, d = rem % D;
    Wt[(size_t)f * (HEADS * D) + h * D + d] = __float2half(W[idx]);
}

// ---------------------------------------------------------------------------
// Tensor-core GEMM: C[GN, Kout] = A[GN, Kin] @ B[Kin, Kout], fp16 in,
// fp32 accum, fp16 out. BM=64, BN=128, BK=32; 8 warps (2x4), warp tile 32x32.
// ---------------------------------------------------------------------------
#define BM 64
#define BN 128
#define BK 32

__device__ __forceinline__ uint32_t smem_u32(const void* p) {
    return (uint32_t)__cvta_generic_to_shared(p);
}

__global__ __launch_bounds__(256) void gemm_tc(
    const __half* __restrict__ A, const __half* __restrict__ B,
    __half* __restrict__ C, int Kin, int Kout)
{
    __shared__ __half As[BM][BK + 8];       // stride 40 halves (80B)
    __shared__ __half Bs[BK][BN + 8];       // stride 136 halves (272B)
    int tid  = threadIdx.x;
    int warp = tid >> 5, lane = tid & 31;
    int wm = warp >> 2;          // 0..1
    int wn = warp & 3;           // 0..3
    int row0 = blockIdx.y * BM;
    int col0 = blockIdx.x * BN;

    float acc[2][4][4];
    #pragma unroll
    for (int a = 0; a < 2; a++)
        #pragma unroll
        for (int b = 0; b < 4; b++)
            #pragma unroll
            for (int c = 0; c < 4; c++) acc[a][b][c] = 0.f;

    int ar = tid >> 2, ac = (tid & 3) * 8;

    for (int k0 = 0; k0 < Kin; k0 += BK) {
        *(uint4*)&As[ar][ac] = *(const uint4*)&A[(size_t)(row0 + ar) * Kin + k0 + ac];
        #pragma unroll
        for (int s = 0; s < 2; s++) {
            int seg = tid + s * 256;
            int br = seg >> 4, bc = (seg & 15) * 8;
            *(uint4*)&Bs[br][bc] = *(const uint4*)&B[(size_t)(k0 + br) * Kout + col0 + bc];
        }
        __syncthreads();

        #pragma unroll
        for (int kk = 0; kk < 2; kk++) {
            uint32_t afr[2][4];
            #pragma unroll
            for (int mt = 0; mt < 2; mt++) {
                int r = wm * 32 + mt * 16 + (lane & 15);
                int c = kk * 16 + (lane >> 4) * 8;
                uint32_t addr = smem_u32(&As[r][c]);
                asm volatile(
                    "ldmatrix.sync.aligned.m8n8.x4.shared.b16 {%0,%1,%2,%3}, [%4];"
                    : "=r"(afr[mt][0]), "=r"(afr[mt][1]),
                      "=r"(afr[mt][2]), "=r"(afr[mt][3]) : "r"(addr));
            }
            uint32_t bfr[4][2];
            #pragma unroll
            for (int p = 0; p < 2; p++) {
                int r = kk * 16 + (lane & 15);
                int c = wn * 32 + p * 16 + (lane >> 4) * 8;
                uint32_t addr = smem_u32(&Bs[r][c]);
                uint32_t r0, r1, r2, r3;
                asm volatile(
                    "ldmatrix.sync.aligned.m8n8.x4.trans.shared.b16 {%0,%1,%2,%3}, [%4];"
                    : "=r"(r0), "=r"(r1), "=r"(r2), "=r"(r3) : "r"(addr));
                bfr[p * 2][0] = r0;     bfr[p * 2][1] = r1;
                bfr[p * 2 + 1][0] = r2; bfr[p * 2 + 1][1] = r3;
            }
            #pragma unroll
            for (int mt = 0; mt < 2; mt++)
                #pragma unroll
                for (int nt = 0; nt < 4; nt++) {
                    asm volatile(
                        "mma.sync.aligned.m16n8k16.row.col.f32.f16.f16.f32 "
                        "{%0,%1,%2,%3}, {%4,%5,%6,%7}, {%8,%9}, {%0,%1,%2,%3};"
                        : "+f"(acc[mt][nt][0]), "+f"(acc[mt][nt][1]),
                          "+f"(acc[mt][nt][2]), "+f"(acc[mt][nt][3])
                        : "r"(afr[mt][0]), "r"(afr[mt][1]),
                          "r"(afr[mt][2]), "r"(afr[mt][3]),
                          "r"(bfr[nt][0]), "r"(bfr[nt][1]));
                }
        }
        __syncthreads();
    }

    int g = lane >> 2, t4 = lane & 3;
    #pragma unroll
    for (int mt = 0; mt < 2; mt++)
        #pragma unroll
        for (int nt = 0; nt < 4; nt++) {
            int r = row0 + wm * 32 + mt * 16;
            int c = col0 + wn * 32 + nt * 8 + t4 * 2;
            __half2 lo = __floats2half2_rn(acc[mt][nt][0], acc[mt][nt][1]);
            __half2 hi = __floats2half2_rn(acc[mt][nt][2], acc[mt][nt][3]);
            *(__half2*)&C[(size_t)(r + g)     * Kout + c] = lo;
            *(__half2*)&C[(size_t)(r + g + 8) * Kout + c] = hi;
        }
}

// ---------------------------------------------------------------------------
// Attention scores: warp per (node, head), fp16 Wh reads, fp32 math.
// ---------------------------------------------------------------------------
__global__ __launch_bounds__(256) void score_kernel(
    const __half* __restrict__ WhH, const float* __restrict__ a_src,
    const float* __restrict__ a_dst, float* __restrict__ s,
    float* __restrict__ t, int D)
{
    int warp = (blockIdx.x * blockDim.x + threadIdx.x) >> 5;
    if (warp >= GN * HEADS) return;
    int lane = threadIdx.x & 31;
    int n = warp >> 2;
    int h = warp & 3;
    int K = HEADS * D;
    const __half2* row = (const __half2*)(WhH + (size_t)n * K + h * D);
    float ss = 0.f, tt = 0.f;
    for (int d = lane; d < (D >> 1); d += 32) {
        float2 v = __half22float2(row[d]);
        float asx = a_src[h * D + 2 * d], asy = a_src[h * D + 2 * d + 1];
        float adx = a_dst[h * D + 2 * d], ady = a_dst[h * D + 2 * d + 1];
        ss += v.x * asx + v.y * asy;
        tt += v.x * adx + v.y * ady;
    }
    #pragma unroll
    for (int o = 16; o; o >>= 1) {
        ss += __shfl_xor_sync(0xffffffffu, ss, o);
        tt += __shfl_xor_sync(0xffffffffu, tt, o);
    }
    if (lane == 0) { s[h * GN + n] = ss; t[h * GN + n] = tt; }
}

// ---------------------------------------------------------------------------
// Sparse softmax + aggregation. Block (256) per destination node.
// Each thread owns 8 consecutive channels (uint4 = 8 halves per neighbor),
// G neighbor groups reduced via smem. Writes fp16 (concat) or fp32 (mean).
// ---------------------------------------------------------------------------
__global__ __launch_bounds__(256) void agg_kernel(
    const __half* __restrict__ WhH, const float* __restrict__ s,
    const float* __restrict__ t, void* __restrict__ outp,
    int D, int meanMode)
{
    int K   = HEADS * D;          // 256 or 512
    int CPS = K >> 3;             // threads per neighbor-slice: 32 or 64
    int G   = 256 / CPS;          // neighbor groups: 8 or 4
    __shared__ int   sidx[PAD];
    __shared__ float sw[HEADS][PAD];
    __shared__ float sz[HEADS], ssrc[HEADS];
    __shared__ float buf[2048];   // [G][K]

    int i   = blockIdx.x;
    int tid = threadIdx.x;
    int sl  = tid % CPS;
    int g   = tid / CPS;
    int c8  = sl * 8;
    int h   = c8 / D;

    if (tid < HEADS) ssrc[tid] = s[tid * GN + i];
    int cnt = g_cnt[i];
    if (tid < cnt) sidx[tid] = g_col_idx[i * PAD + tid];
    __syncthreads();

    if (tid < cnt) {
        int j = sidx[tid];
        #pragma unroll
        for (int hh = 0; hh < HEADS; hh++) {
            float z = ssrc[hh] + t[hh * GN + j];
            sw[hh][tid] = (z > 0.f) ? z : 0.2f * z;
        }
    }
    __syncthreads();

    {   // softmax per head: warp w -> head w
        int wid = tid >> 5, lane = tid & 31;
        if (wid < HEADS) {
            int hh = wid;
            float mx = -CUDART_INF_F;
            for (int k = lane; k < cnt; k += 32) mx = fmaxf(mx, sw[hh][k]);
            #pragma unroll
            for (int o = 16; o; o >>= 1)
                mx = fmaxf(mx, __shfl_xor_sync(0xffffffffu, mx, o));
            float lz = 0.f;
            for (int k = lane; k < cnt; k += 32) {
                float w = __expf(sw[hh][k] - mx);
                sw[hh][k] = w;
                lz += w;
            }
            #pragma unroll
            for (int o = 16; o; o >>= 1) lz += __shfl_xor_sync(0xffffffffu, lz, o);
            if (lane == 0) sz[hh] = lz;
        }
    }
    __syncthreads();

    float acc[8] = {};
    const float* swh = sw[h];
    for (int k = g; k < cnt; k += G) {
        float w = swh[k];
        uint4 v = *(const uint4*)&WhH[(size_t)sidx[k] * K + c8];
        float2 p0 = __half22float2(*(__half2*)&v.x);
        float2 p1 = __half22float2(*(__half2*)&v.y);
        float2 p2 = __half22float2(*(__half2*)&v.z);
        float2 p3 = __half22float2(*(__half2*)&v.w);
        acc[0] += w * p0.x; acc[1] += w * p0.y;
        acc[2] += w * p1.x; acc[3] += w * p1.y;
        acc[4] += w * p2.x; acc[5] += w * p2.y;
        acc[6] += w * p3.x; acc[7] += w * p3.y;
    }
    float* bg = buf + g * K + c8;
    #pragma unroll
    for (int q = 0; q < 8; q++) bg[q] = acc[q];
    __syncthreads();

    if (!meanMode) {
        // K=256: one channel per thread; combine G=8 groups, ELU, fp16 out
        __half* out = (__half*)outp;
        int c = tid;
        float v = 0.f;
        for (int gg = 0; gg < G; gg++) v += buf[gg * K + c];
        v /= sz[c / D];
        v = (v > 0.f) ? v : (__expf(v) - 1.f);
        out[(size_t)i * K + c] = __float2half(v);
    } else {
        // K=512: head mean, no ELU, fp32 out [N, D]
        float* out = (float*)outp;
        if (tid < D) {
            float v = 0.f;
            #pragma unroll
            for (int hh = 0; hh < HEADS; hh++) {
                float hv = 0.f;
                for (int gg = 0; gg < G; gg++) hv += buf[gg * K + hh * D + tid];
                v += hv / sz[hh];
            }
            out[(size_t)i * D + tid] = 0.25f * v;
        }
    }
}

// ---------------------------------------------------------------------------
extern "C" void kernel_launch(void* const* d_in, const int* in_sizes, int n_in,
                              void* d_out, int out_size)
{
    const float* x   = (const float*)d_in[0];
    const void*  adj =               d_in[1];
    const float* W0  = (const float*)d_in[2];
    const float* a0s = (const float*)d_in[3];
    const float* a0d = (const float*)d_in[4];
    const float* W1  = (const float*)d_in[5];
    const float* a1s = (const float*)d_in[6];
    const float* a1d = (const float*)d_in[7];
    const float* W2  = (const float*)d_in[8];
    const float* a2s = (const float*)d_in[9];
    const float* a2d = (const float*)d_in[10];
    float* out = (float*)d_out;

    __half *pxh, *pWt, *pWhH, *phH;
    float  *ps, *pt;
    cudaGetSymbolAddress((void**)&pxh,  g_xh);
    cudaGetSymbolAddress((void**)&pWt,  g_Wt);
    cudaGetSymbolAddress((void**)&pWhH, g_WhH);
    cudaGetSymbolAddress((void**)&phH,  g_hH);
    cudaGetSymbolAddress((void**)&ps,   g_s);
    cudaGetSymbolAddress((void**)&pt,   g_t);

    detect_kernel<<<1, 256>>>((const unsigned char*)adj);
    csr_build<<<GN / 8, 256>>>(adj);
    conv_x<<<GN * 256 / 4 / 256, 256>>>(x, pxh, GN * 64);

    int score_blocks = (GN * HEADS * 32) / 256;
    dim3 gL01(2, GN / BM);   // Kout=256
    dim3 gL2 (4, GN / BM);   // Kout=512

    // Layer 0
    conv_w<<<(HEADS * 256 * 64 + 255) / 256, 256>>>(W0, pWt, 256, 64);
    gemm_tc<<<gL01, 256>>>(pxh, pWt, pWhH, 256, 256);
    score_kernel<<<score_blocks, 256>>>(pWhH, a0s, a0d, ps, pt, 64);
    agg_kernel<<<GN, 256>>>(pWhH, ps, pt, phH, 64, 0);

    // Layer 1
    conv_w<<<(HEADS * 256 * 64 + 255) / 256, 256>>>(W1, pWt, 256, 64);
    gemm_tc<<<gL01, 256>>>(phH, pWt, pWhH, 256, 256);
    score_kernel<<<score_blocks, 256>>>(pWhH, a1s, a1d, ps, pt, 64);
    agg_kernel<<<GN, 256>>>(pWhH, ps, pt, phH, 64, 0);

    // Layer 2 (head mean, no ELU, fp32 out)
    conv_w<<<(HEADS * 256 * 128 + 255) / 256, 256>>>(W2, pWt, 256, 128);
    gemm_tc<<<gL2, 256>>>(phH, pWt, pWhH, 256, 512);
    score_kernel<<<score_blocks, 256>>>(pWhH, a2s, a2d, ps, pt, 128);
    agg_kernel<<<GN, 256>>>(pWhH, ps, pt, out, 128, 1);
}

// round 4
// speedup vs baseline: 2.4240x; 1.1884x over previous
#include <cuda_runtime.h>
#include <cuda_fp16.h>
#include <cstdint>
#include <math_constants.h>

// ---------------------------------------------------------------------------
// GAT, 3 layers, N=4096, F_IN=256, HID=256, OUT=128, HEADS=4.
// Round 4: cp.async double-buffered fp16 MMA GEMM with fused score epilogue
// (fp32 accum), single prep kernel, CSR overlapped via stream fork/join.
// ---------------------------------------------------------------------------

#define GN    4096
#define HEADS 4
#define PAD   128
#define BM    64
#define BN    128
#define BK    32

__device__ __half g_xh [GN * 256];
__device__ __half g_W0h[256 * 256];
__device__ __half g_W1h[256 * 256];
__device__ __half g_W2h[256 * 512];
__device__ __half g_WhH[GN * 512];
__device__ __half g_hH [GN * 256];
__device__ float  g_s  [HEADS * GN];
__device__ float  g_t  [HEADS * GN];
__device__ int    g_cnt[GN];
__device__ int    g_col_idx[GN * PAD];
__device__ int    g_byte_mode;

// ---------------------------------------------------------------------------
// Adjacency dtype detection (64KB scan).
// ---------------------------------------------------------------------------
__global__ void detect_kernel(const unsigned char* __restrict__ adj) {
    __shared__ int s_mis, s_b0;
    if (threadIdx.x == 0) { s_mis = 0; s_b0 = 0; }
    __syncthreads();
    int mis = 0, b0 = 0;
    for (int off = threadIdx.x; off < (1 << 16); off += blockDim.x) {
        unsigned char v = adj[off];
        if (v) { if (off & 3) mis++; else b0++; }
    }
    if (mis) atomicAdd(&s_mis, mis);
    if (b0)  atomicAdd(&s_b0, b0);
    __syncthreads();
    if (threadIdx.x == 0) g_byte_mode = (s_mis > 0 && s_b0 > 0) ? 1 : 0;
}

// ---------------------------------------------------------------------------
// One-pass padded CSR build (warp/row, uint4 loads, shfl-scan ordering).
// ---------------------------------------------------------------------------
__device__ __forceinline__ int warp_excl_scan(int v, int lane, int& tot) {
    int p = v;
    #pragma unroll
    for (int o = 1; o < 32; o <<= 1) {
        int x = __shfl_up_sync(0xffffffffu, p, o);
        if (lane >= o) p += x;
    }
    tot = __shfl_sync(0xffffffffu, p, 31);
    return p - v;
}

__global__ __launch_bounds__(256) void csr_build(const void* __restrict__ adj) {
    int warp = (blockIdx.x * blockDim.x + threadIdx.x) >> 5;
    if (warp >= GN) return;
    int lane = threadIdx.x & 31;
    int r    = warp;
    int base = r * PAD;
    int total = 0;
    int lim = base + PAD;

    if (!g_byte_mode) {
        const uint4* p = (const uint4*)adj + (size_t)r * 1024;
        for (int it = 0; it < 32; it++) {
            uint4 v = p[it * 32 + lane];
            int b0 = (v.x != 0u), b1 = (v.y != 0u), b2 = (v.z != 0u), b3 = (v.w != 0u);
            int own = b0 + b1 + b2 + b3;
            int tot;
            int excl = warp_excl_scan(own, lane, tot);
            int pos = base + total + excl;
            int c0 = it * 128 + lane * 4;
            if (b0) { if (pos < lim) g_col_idx[pos] = c0 + 0; pos++; }
            if (b1) { if (pos < lim) g_col_idx[pos] = c0 + 1; pos++; }
            if (b2) { if (pos < lim) g_col_idx[pos] = c0 + 2; pos++; }
            if (b3) { if (pos < lim) g_col_idx[pos] = c0 + 3; pos++; }
            total += tot;
        }
    } else {
        const uint4* p = (const uint4*)adj + (size_t)r * 256;
        for (int it = 0; it < 8; it++) {
            uint4 v = p[it * 32 + lane];
            unsigned w[4] = {v.x, v.y, v.z, v.w};
            int own = 0;
            #pragma unroll
            for (int q = 0; q < 4; q++)
                #pragma unroll
                for (int b = 0; b < 4; b++)
                    own += ((w[q] >> (8 * b)) & 0xFFu) ? 1 : 0;
            int tot;
            int excl = warp_excl_scan(own, lane, tot);
            int pos = base + total + excl;
            int c0 = it * 512 + lane * 16;
            #pragma unroll
            for (int q = 0; q < 4; q++)
                #pragma unroll
                for (int b = 0; b < 4; b++)
                    if ((w[q] >> (8 * b)) & 0xFFu) {
                        if (pos < lim) g_col_idx[pos] = c0 + q * 4 + b;
                        pos++;
                    }
            total += tot;
        }
    }
    if (lane == 0) g_cnt[r] = (total < PAD) ? total : PAD;
}

// ---------------------------------------------------------------------------
// Prep: convert x -> fp16, and W0/W1/W2 [H][F][D] fp32 -> [F][H*D] fp16.
// One kernel, disjoint index ranges.
// ---------------------------------------------------------------------------
__global__ __launch_bounds__(256) void prep(
    const float* __restrict__ x,  const float* __restrict__ W0,
    const float* __restrict__ W1, const float* __restrict__ W2,
    __half* __restrict__ xh, __half* __restrict__ w0,
    __half* __restrict__ w1, __half* __restrict__ w2)
{
    int idx = blockIdx.x * 256 + threadIdx.x;
    const int NX4 = GN * 256 / 4;              // 262144 float4s of x
    if (idx < NX4) {
        float4 v = ((const float4*)x)[idx];
        ((__half2*)xh)[2 * idx]     = __floats2half2_rn(v.x, v.y);
        ((__half2*)xh)[2 * idx + 1] = __floats2half2_rn(v.z, v.w);
        return;
    }
    int i0 = idx - NX4;
    if (i0 < 65536) {                           // W0: F=256, D=64
        int h = i0 >> 14, rem = i0 & 16383, f = rem >> 6, d = rem & 63;
        w0[f * 256 + h * 64 + d] = __float2half(W0[i0]);
        return;
    }
    int i1 = i0 - 65536;
    if (i1 < 65536) {                           // W1
        int h = i1 >> 14, rem = i1 & 16383, f = rem >> 6, d = rem & 63;
        w1[f * 256 + h * 64 + d] = __float2half(W1[i1]);
        return;
    }
    int i2 = i1 - 65536;
    if (i2 < 131072) {                          // W2: F=256, D=128
        int h = i2 >> 15, rem = i2 & 32767, f = rem >> 7, d = rem & 127;
        w2[f * 512 + h * 128 + d] = __float2half(W2[i2]);
    }
}

// ---------------------------------------------------------------------------
// GEMM + fused attention scores.
// C[GN,Kout] = A @ B (fp16 in, fp32 accum, fp16 out), plus
// s[h,n] = sum_d C[n,h*D+d]*a_src[h*D+d], t likewise, from fp32 accums.
// BM=64, BN=128, BK=32, 8 warps (2Mx4N), warp tile 32x32, cp.async 2-stage.
// ---------------------------------------------------------------------------
__device__ __forceinline__ uint32_t smem_u32(const void* p) {
    return (uint32_t)__cvta_generic_to_shared(p);
}

__global__ __launch_bounds__(256) void gemm_fused(
    const __half* __restrict__ A, const __half* __restrict__ B,
    __half* __restrict__ C, const float* __restrict__ a_src,
    const float* __restrict__ a_dst, float* __restrict__ s,
    float* __restrict__ t, int Kin, int Kout, int D)
{
    __shared__ __align__(16) __half As[2][BM][BK + 8];
    __shared__ __align__(16) __half Bs[2][BK][BN + 8];
    __shared__ float s_sm[4][BM], t_sm[4][BM];
    __shared__ float a_s[BN], a_d[BN];

    int tid  = threadIdx.x;
    int warp = tid >> 5, lane = tid & 31;
    int wm = warp >> 2;          // 0..1
    int wn = warp & 3;           // 0..3
    int row0 = blockIdx.y * BM;
    int col0 = blockIdx.x * BN;

    if (tid < BN) { a_s[tid] = a_src[col0 + tid]; a_d[tid] = a_dst[col0 + tid]; }

    float acc[2][4][4] = {};

    int ar = tid >> 2, ac = (tid & 3) * 8;

    #define LOAD_STAGE(st, k0)                                                 \
    {                                                                          \
        uint32_t da = smem_u32(&As[st][ar][ac]);                               \
        asm volatile("cp.async.cg.shared.global [%0], [%1], 16;"               \
                     :: "r"(da), "l"(A + (size_t)(row0 + ar) * Kin + (k0) + ac)); \
        _Pragma("unroll")                                                      \
        for (int ss = 0; ss < 2; ss++) {                                       \
            int seg = tid + ss * 256;                                          \
            int br = seg >> 4, bc = (seg & 15) * 8;                            \
            uint32_t db = smem_u32(&Bs[st][br][bc]);                           \
            asm volatile("cp.async.cg.shared.global [%0], [%1], 16;"           \
                         :: "r"(db), "l"(B + (size_t)((k0) + br) * Kout + col0 + bc)); \
        }                                                                      \
        asm volatile("cp.async.commit_group;");                                \
    }

    int KT = Kin / BK;   // 8
    LOAD_STAGE(0, 0);

    for (int kt = 0; kt < KT; kt++) {
        int cur = kt & 1;
        if (kt + 1 < KT) {
            LOAD_STAGE(cur ^ 1, (kt + 1) * BK);
            asm volatile("cp.async.wait_group 1;");
        } else {
            asm volatile("cp.async.wait_group 0;");
        }
        __syncthreads();

        #pragma unroll
        for (int kk = 0; kk < 2; kk++) {
            uint32_t afr[2][4];
            #pragma unroll
            for (int mt = 0; mt < 2; mt++) {
                int r = wm * 32 + mt * 16 + (lane & 15);
                int c = kk * 16 + (lane >> 4) * 8;
                uint32_t addr = smem_u32(&As[cur][r][c]);
                asm volatile(
                    "ldmatrix.sync.aligned.m8n8.x4.shared.b16 {%0,%1,%2,%3}, [%4];"
                    : "=r"(afr[mt][0]), "=r"(afr[mt][1]),
                      "=r"(afr[mt][2]), "=r"(afr[mt][3]) : "r"(addr));
            }
            uint32_t bfr[4][2];
            #pragma unroll
            for (int p = 0; p < 2; p++) {
                int r = kk * 16 + (lane & 15);
                int c = wn * 32 + p * 16 + (lane >> 4) * 8;
                uint32_t addr = smem_u32(&Bs[cur][r][c]);
                uint32_t r0, r1, r2, r3;
                asm volatile(
                    "ldmatrix.sync.aligned.m8n8.x4.trans.shared.b16 {%0,%1,%2,%3}, [%4];"
                    : "=r"(r0), "=r"(r1), "=r"(r2), "=r"(r3) : "r"(addr));
                bfr[p * 2][0] = r0;     bfr[p * 2][1] = r1;
                bfr[p * 2 + 1][0] = r2; bfr[p * 2 + 1][1] = r3;
            }
            #pragma unroll
            for (int mt = 0; mt < 2; mt++)
                #pragma unroll
                for (int nt = 0; nt < 4; nt++) {
                    asm volatile(
                        "mma.sync.aligned.m16n8k16.row.col.f32.f16.f16.f32 "
                        "{%0,%1,%2,%3}, {%4,%5,%6,%7}, {%8,%9}, {%0,%1,%2,%3};"
                        : "+f"(acc[mt][nt][0]), "+f"(acc[mt][nt][1]),
                          "+f"(acc[mt][nt][2]), "+f"(acc[mt][nt][3])
                        : "r"(afr[mt][0]), "r"(afr[mt][1]),
                          "r"(afr[mt][2]), "r"(afr[mt][3]),
                          "r"(bfr[nt][0]), "r"(bfr[nt][1]));
                }
        }
        __syncthreads();
    }
    #undef LOAD_STAGE

    // epilogue: fp16 store + score partials from fp32 accums
    int g = lane >> 2, t4 = lane & 3;
    float sp[2][2] = {}, tp[2][2] = {};
    #pragma unroll
    for (int mt = 0; mt < 2; mt++)
        #pragma unroll
        for (int nt = 0; nt < 4; nt++) {
            int cl = wn * 32 + nt * 8 + t4 * 2;
            int r  = row0 + wm * 32 + mt * 16;
            int c  = col0 + cl;
            __half2 lo = __floats2half2_rn(acc[mt][nt][0], acc[mt][nt][1]);
            __half2 hi = __floats2half2_rn(acc[mt][nt][2], acc[mt][nt][3]);
            *(__half2*)&C[(size_t)(r + g)     * Kout + c] = lo;
            *(__half2*)&C[(size_t)(r + g + 8) * Kout + c] = hi;
            float s0 = a_s[cl], s1 = a_s[cl + 1];
            float d0 = a_d[cl], d1 = a_d[cl + 1];
            sp[mt][0] += acc[mt][nt][0] * s0 + acc[mt][nt][1] * s1;
            sp[mt][1] += acc[mt][nt][2] * s0 + acc[mt][nt][3] * s1;
            tp[mt][0] += acc[mt][nt][0] * d0 + acc[mt][nt][1] * d1;
            tp[mt][1] += acc[mt][nt][2] * d0 + acc[mt][nt][3] * d1;
        }
    #pragma unroll
    for (int o = 1; o <= 2; o <<= 1)
        #pragma unroll
        for (int mt = 0; mt < 2; mt++) {
            sp[mt][0] += __shfl_xor_sync(0xffffffffu, sp[mt][0], o);
            sp[mt][1] += __shfl_xor_sync(0xffffffffu, sp[mt][1], o);
            tp[mt][0] += __shfl_xor_sync(0xffffffffu, tp[mt][0], o);
            tp[mt][1] += __shfl_xor_sync(0xffffffffu, tp[mt][1], o);
        }
    if (t4 == 0)
        #pragma unroll
        for (int mt = 0; mt < 2; mt++) {
            int r = wm * 32 + mt * 16 + g;
            s_sm[wn][r]     = sp[mt][0];  s_sm[wn][r + 8] = sp[mt][1];
            t_sm[wn][r]     = tp[mt][0];  t_sm[wn][r + 8] = tp[mt][1];
        }
    __syncthreads();
    if (tid < BM) {
        int r = row0 + tid;
        if (D == 64) {
            int h0 = col0 >> 6;
            s[h0 * GN + r]       = s_sm[0][tid] + s_sm[1][tid];
            s[(h0 + 1) * GN + r] = s_sm[2][tid] + s_sm[3][tid];
            t[h0 * GN + r]       = t_sm[0][tid] + t_sm[1][tid];
            t[(h0 + 1) * GN + r] = t_sm[2][tid] + t_sm[3][tid];
        } else {
            int h = col0 >> 7;
            s[h * GN + r] = s_sm[0][tid] + s_sm[1][tid] + s_sm[2][tid] + s_sm[3][tid];
            t[h * GN + r] = t_sm[0][tid] + t_sm[1][tid] + t_sm[2][tid] + t_sm[3][tid];
        }
    }
}

// ---------------------------------------------------------------------------
// Sparse softmax + aggregation (unchanged from round 3).
// ---------------------------------------------------------------------------
__global__ __launch_bounds__(256) void agg_kernel(
    const __half* __restrict__ WhH, const float* __restrict__ s,
    const float* __restrict__ t, void* __restrict__ outp,
    int D, int meanMode)
{
    int K   = HEADS * D;
    int CPS = K >> 3;
    int G   = 256 / CPS;
    __shared__ int   sidx[PAD];
    __shared__ float sw[HEADS][PAD];
    __shared__ float sz[HEADS], ssrc[HEADS];
    __shared__ float buf[2048];

    int i   = blockIdx.x;
    int tid = threadIdx.x;
    int sl  = tid % CPS;
    int g   = tid / CPS;
    int c8  = sl * 8;
    int h   = c8 / D;

    if (tid < HEADS) ssrc[tid] = s[tid * GN + i];
    int cnt = g_cnt[i];
    if (tid < cnt) sidx[tid] = g_col_idx[i * PAD + tid];
    __syncthreads();

    if (tid < cnt) {
        int j = sidx[tid];
        #pragma unroll
        for (int hh = 0; hh < HEADS; hh++) {
            float z = ssrc[hh] + t[hh * GN + j];
            sw[hh][tid] = (z > 0.f) ? z : 0.2f * z;
        }
    }
    __syncthreads();

    {
        int wid = tid >> 5, lane = tid & 31;
        if (wid < HEADS) {
            int hh = wid;
            float mx = -CUDART_INF_F;
            for (int k = lane; k < cnt; k += 32) mx = fmaxf(mx, sw[hh][k]);
            #pragma unroll
            for (int o = 16; o; o >>= 1)
                mx = fmaxf(mx, __shfl_xor_sync(0xffffffffu, mx, o));
            float lz = 0.f;
            for (int k = lane; k < cnt; k += 32) {
                float w = __expf(sw[hh][k] - mx);
                sw[hh][k] = w;
                lz += w;
            }
            #pragma unroll
            for (int o = 16; o; o >>= 1) lz += __shfl_xor_sync(0xffffffffu, lz, o);
            if (lane == 0) sz[hh] = lz;
        }
    }
    __syncthreads();

    float acc[8] = {};
    const float* swh = sw[h];
    for (int k = g; k < cnt; k += G) {
        float w = swh[k];
        uint4 v = *(const uint4*)&WhH[(size_t)sidx[k] * K + c8];
        float2 p0 = __half22float2(*(__half2*)&v.x);
        float2 p1 = __half22float2(*(__half2*)&v.y);
        float2 p2 = __half22float2(*(__half2*)&v.z);
        float2 p3 = __half22float2(*(__half2*)&v.w);
        acc[0] += w * p0.x; acc[1] += w * p0.y;
        acc[2] += w * p1.x; acc[3] += w * p1.y;
        acc[4] += w * p2.x; acc[5] += w * p2.y;
        acc[6] += w * p3.x; acc[7] += w * p3.y;
    }
    float* bg = buf + g * K + c8;
    #pragma unroll
    for (int q = 0; q < 8; q++) bg[q] = acc[q];
    __syncthreads();

    if (!meanMode) {
        __half* out = (__half*)outp;
        int c = tid;
        float v = 0.f;
        for (int gg = 0; gg < G; gg++) v += buf[gg * K + c];
        v /= sz[c / D];
        v = (v > 0.f) ? v : (__expf(v) - 1.f);
        out[(size_t)i * K + c] = __float2half(v);
    } else {
        float* out = (float*)outp;
        if (tid < D) {
            float v = 0.f;
            #pragma unroll
            for (int hh = 0; hh < HEADS; hh++) {
                float hv = 0.f;
                for (int gg = 0; gg < G; gg++) hv += buf[gg * K + hh * D + tid];
                v += hv / sz[hh];
            }
            out[(size_t)i * D + tid] = 0.25f * v;
        }
    }
}

// ---------------------------------------------------------------------------
extern "C" void kernel_launch(void* const* d_in, const int* in_sizes, int n_in,
                              void* d_out, int out_size)
{
    const float* x   = (const float*)d_in[0];
    const void*  adj =               d_in[1];
    const float* W0  = (const float*)d_in[2];
    const float* a0s = (const float*)d_in[3];
    const float* a0d = (const float*)d_in[4];
    const float* W1  = (const float*)d_in[5];
    const float* a1s = (const float*)d_in[6];
    const float* a1d = (const float*)d_in[7];
    const float* W2  = (const float*)d_in[8];
    const float* a2s = (const float*)d_in[9];
    const float* a2d = (const float*)d_in[10];
    float* out = (float*)d_out;

    __half *pxh, *pW0, *pW1, *pW2, *pWhH, *phH;
    float  *ps, *pt;
    cudaGetSymbolAddress((void**)&pxh,  g_xh);
    cudaGetSymbolAddress((void**)&pW0,  g_W0h);
    cudaGetSymbolAddress((void**)&pW1,  g_W1h);
    cudaGetSymbolAddress((void**)&pW2,  g_W2h);
    cudaGetSymbolAddress((void**)&pWhH, g_WhH);
    cudaGetSymbolAddress((void**)&phH,  g_hH);
    cudaGetSymbolAddress((void**)&ps,   g_s);
    cudaGetSymbolAddress((void**)&pt,   g_t);

    static cudaStream_t sB = 0;
    static cudaEvent_t  eFork = 0, eJoin = 0;
    if (!sB) {
        cudaStreamCreateWithFlags(&sB, cudaStreamNonBlocking);
        cudaEventCreateWithFlags(&eFork, cudaEventDisableTiming);
        cudaEventCreateWithFlags(&eJoin, cudaEventDisableTiming);
    }

    // fork: projections on sB, CSR build on main stream
    cudaEventRecord(eFork, 0);
    cudaStreamWaitEvent(sB, eFork, 0);

    prep<<<2048, 256, 0, sB>>>(x, W0, W1, W2, pxh, pW0, pW1, pW2);
    gemm_fused<<<dim3(2, GN / BM), 256, 0, sB>>>(pxh, pW0, pWhH, a0s, a0d,
                                                 ps, pt, 256, 256, 64);
    cudaEventRecord(eJoin, sB);

    detect_kernel<<<1, 256>>>((const unsigned char*)adj);
    csr_build<<<GN / 8, 256>>>(adj);
    cudaStreamWaitEvent(0, eJoin, 0);

    // Layer 0 aggregation
    agg_kernel<<<GN, 256>>>(pWhH, ps, pt, phH, 64, 0);

    // Layer 1
    gemm_fused<<<dim3(2, GN / BM), 256>>>(phH, pW1, pWhH, a1s, a1d,
                                          ps, pt, 256, 256, 64);
    agg_kernel<<<GN, 256>>>(pWhH, ps, pt, phH, 64, 0);

    // Layer 2 (head mean, no ELU, fp32 out)
    gemm_fused<<<dim3(4, GN / BM), 256>>>(phH, pW2, pWhH, a2s, a2d,
                                          ps, pt, 256, 512, 128);
    agg_kernel<<<GN, 256>>>(pWhH, ps, pt, out, 128, 1);
}

// round 5
// speedup vs baseline: 2.4864x; 1.0258x over previous
#include <cuda_runtime.h>
#include <cuda_fp16.h>
#include <cstdint>
#include <math_constants.h>

// ---------------------------------------------------------------------------
// GAT, 3 layers, N=4096, F_IN=256, HID=256, OUT=128, HEADS=4.
// Round 5: MLP-batched CSR build; interleaved s/t layout (float4 gathers in
// agg); cp.async fp16 MMA GEMM with fused score epilogue; stream fork/join.
// ---------------------------------------------------------------------------

#define GN    4096
#define HEADS 4
#define PAD   128
#define BM    64
#define BN    128
#define BK    32

__device__ __half g_xh [GN * 256];
__device__ __half g_W0h[256 * 256];
__device__ __half g_W1h[256 * 256];
__device__ __half g_W2h[256 * 512];
__device__ __half g_WhH[GN * 512];
__device__ __half g_hH [GN * 256];
__device__ float  g_st [GN * 8];      // [n][0..3]=s per head, [n][4..7]=t per head
__device__ int    g_cnt[GN];
__device__ int    g_col_idx[GN * PAD];
__device__ int    g_byte_mode;

// ---------------------------------------------------------------------------
// Adjacency dtype detection (64KB scan).
// ---------------------------------------------------------------------------
__global__ void detect_kernel(const unsigned char* __restrict__ adj) {
    __shared__ int s_mis, s_b0;
    if (threadIdx.x == 0) { s_mis = 0; s_b0 = 0; }
    __syncthreads();
    int mis = 0, b0 = 0;
    for (int off = threadIdx.x; off < (1 << 16); off += blockDim.x) {
        unsigned char v = adj[off];
        if (v) { if (off & 3) mis++; else b0++; }
    }
    if (mis) atomicAdd(&s_mis, mis);
    if (b0)  atomicAdd(&s_b0, b0);
    __syncthreads();
    if (threadIdx.x == 0) g_byte_mode = (s_mis > 0 && s_b0 > 0) ? 1 : 0;
}

// ---------------------------------------------------------------------------
// One-pass padded CSR build, MLP-batched: 4 independent uint4 loads issued
// before each scan quartet (memory-level parallelism ~4).
// ---------------------------------------------------------------------------
__device__ __forceinline__ int warp_excl_scan(int v, int lane, int& tot) {
    int p = v;
    #pragma unroll
    for (int o = 1; o < 32; o <<= 1) {
        int x = __shfl_up_sync(0xffffffffu, p, o);
        if (lane >= o) p += x;
    }
    tot = __shfl_sync(0xffffffffu, p, 31);
    return p - v;
}

__global__ __launch_bounds__(256) void csr_build(const void* __restrict__ adj) {
    int warp = (blockIdx.x * blockDim.x + threadIdx.x) >> 5;
    if (warp >= GN) return;
    int lane = threadIdx.x & 31;
    int r    = warp;
    int base = r * PAD;
    int total = 0;
    int lim = base + PAD;

    if (!g_byte_mode) {
        const uint4* p = (const uint4*)adj + (size_t)r * 1024;
        for (int ob = 0; ob < 32; ob += 4) {
            uint4 v[4];
            #pragma unroll
            for (int q = 0; q < 4; q++) v[q] = p[(ob + q) * 32 + lane];
            #pragma unroll
            for (int q = 0; q < 4; q++) {
                int it = ob + q;
                int b0 = (v[q].x != 0u), b1 = (v[q].y != 0u);
                int b2 = (v[q].z != 0u), b3 = (v[q].w != 0u);
                int own = b0 + b1 + b2 + b3;
                int tot;
                int excl = warp_excl_scan(own, lane, tot);
                int pos = base + total + excl;
                int c0 = it * 128 + lane * 4;
                if (b0) { if (pos < lim) g_col_idx[pos] = c0 + 0; pos++; }
                if (b1) { if (pos < lim) g_col_idx[pos] = c0 + 1; pos++; }
                if (b2) { if (pos < lim) g_col_idx[pos] = c0 + 2; pos++; }
                if (b3) { if (pos < lim) g_col_idx[pos] = c0 + 3; pos++; }
                total += tot;
            }
        }
    } else {
        const uint4* p = (const uint4*)adj + (size_t)r * 256;
        for (int ob = 0; ob < 8; ob += 4) {
            uint4 v[4];
            #pragma unroll
            for (int q = 0; q < 4; q++) v[q] = p[(ob + q) * 32 + lane];
            #pragma unroll
            for (int q = 0; q < 4; q++) {
                int it = ob + q;
                unsigned w[4] = {v[q].x, v[q].y, v[q].z, v[q].w};
                int own = 0;
                #pragma unroll
                for (int u = 0; u < 4; u++)
                    #pragma unroll
                    for (int b = 0; b < 4; b++)
                        own += ((w[u] >> (8 * b)) & 0xFFu) ? 1 : 0;
                int tot;
                int excl = warp_excl_scan(own, lane, tot);
                int pos = base + total + excl;
                int c0 = it * 512 + lane * 16;
                #pragma unroll
                for (int u = 0; u < 4; u++)
                    #pragma unroll
                    for (int b = 0; b < 4; b++)
                        if ((w[u] >> (8 * b)) & 0xFFu) {
                            if (pos < lim) g_col_idx[pos] = c0 + u * 4 + b;
                            pos++;
                        }
                total += tot;
            }
        }
    }
    if (lane == 0) g_cnt[r] = (total < PAD) ? total : PAD;
}

// ---------------------------------------------------------------------------
// Prep: x -> fp16, W0/W1/W2 [H][F][D] fp32 -> [F][H*D] fp16.
// ---------------------------------------------------------------------------
__global__ __launch_bounds__(256) void prep(
    const float* __restrict__ x,  const float* __restrict__ W0,
    const float* __restrict__ W1, const float* __restrict__ W2,
    __half* __restrict__ xh, __half* __restrict__ w0,
    __half* __restrict__ w1, __half* __restrict__ w2)
{
    int idx = blockIdx.x * 256 + threadIdx.x;
    const int NX4 = GN * 256 / 4;
    if (idx < NX4) {
        float4 v = ((const float4*)x)[idx];
        ((__half2*)xh)[2 * idx]     = __floats2half2_rn(v.x, v.y);
        ((__half2*)xh)[2 * idx + 1] = __floats2half2_rn(v.z, v.w);
        return;
    }
    int i0 = idx - NX4;
    if (i0 < 65536) {
        int h = i0 >> 14, rem = i0 & 16383, f = rem >> 6, d = rem & 63;
        w0[f * 256 + h * 64 + d] = __float2half(W0[i0]);
        return;
    }
    int i1 = i0 - 65536;
    if (i1 < 65536) {
        int h = i1 >> 14, rem = i1 & 16383, f = rem >> 6, d = rem & 63;
        w1[f * 256 + h * 64 + d] = __float2half(W1[i1]);
        return;
    }
    int i2 = i1 - 65536;
    if (i2 < 131072) {
        int h = i2 >> 15, rem = i2 & 32767, f = rem >> 7, d = rem & 127;
        w2[f * 512 + h * 128 + d] = __float2half(W2[i2]);
    }
}

// ---------------------------------------------------------------------------
// GEMM + fused attention scores (interleaved st output).
// ---------------------------------------------------------------------------
__device__ __forceinline__ uint32_t smem_u32(const void* p) {
    return (uint32_t)__cvta_generic_to_shared(p);
}

__global__ __launch_bounds__(256) void gemm_fused(
    const __half* __restrict__ A, const __half* __restrict__ B,
    __half* __restrict__ C, const float* __restrict__ a_src,
    const float* __restrict__ a_dst, float* __restrict__ st,
    int Kin, int Kout, int D)
{
    __shared__ __align__(16) __half As[2][BM][BK + 8];
    __shared__ __align__(16) __half Bs[2][BK][BN + 8];
    __shared__ float s_sm[4][BM], t_sm[4][BM];
    __shared__ float a_s[BN], a_d[BN];

    int tid  = threadIdx.x;
    int warp = tid >> 5, lane = tid & 31;
    int wm = warp >> 2;
    int wn = warp & 3;
    int row0 = blockIdx.y * BM;
    int col0 = blockIdx.x * BN;

    if (tid < BN) { a_s[tid] = a_src[col0 + tid]; a_d[tid] = a_dst[col0 + tid]; }

    float acc[2][4][4] = {};
    int ar = tid >> 2, ac = (tid & 3) * 8;

    #define LOAD_STAGE(stg, k0)                                                \
    {                                                                          \
        uint32_t da = smem_u32(&As[stg][ar][ac]);                              \
        asm volatile("cp.async.cg.shared.global [%0], [%1], 16;"               \
                     :: "r"(da), "l"(A + (size_t)(row0 + ar) * Kin + (k0) + ac)); \
        _Pragma("unroll")                                                      \
        for (int ss = 0; ss < 2; ss++) {                                       \
            int seg = tid + ss * 256;                                          \
            int br = seg >> 4, bc = (seg & 15) * 8;                            \
            uint32_t db = smem_u32(&Bs[stg][br][bc]);                          \
            asm volatile("cp.async.cg.shared.global [%0], [%1], 16;"           \
                         :: "r"(db), "l"(B + (size_t)((k0) + br) * Kout + col0 + bc)); \
        }                                                                      \
        asm volatile("cp.async.commit_group;");                                \
    }

    int KT = Kin / BK;
    LOAD_STAGE(0, 0);

    for (int kt = 0; kt < KT; kt++) {
        int cur = kt & 1;
        if (kt + 1 < KT) {
            LOAD_STAGE(cur ^ 1, (kt + 1) * BK);
            asm volatile("cp.async.wait_group 1;");
        } else {
            asm volatile("cp.async.wait_group 0;");
        }
        __syncthreads();

        #pragma unroll
        for (int kk = 0; kk < 2; kk++) {
            uint32_t afr[2][4];
            #pragma unroll
            for (int mt = 0; mt < 2; mt++) {
                int r = wm * 32 + mt * 16 + (lane & 15);
                int c = kk * 16 + (lane >> 4) * 8;
                uint32_t addr = smem_u32(&As[cur][r][c]);
                asm volatile(
                    "ldmatrix.sync.aligned.m8n8.x4.shared.b16 {%0,%1,%2,%3}, [%4];"
                    : "=r"(afr[mt][0]), "=r"(afr[mt][1]),
                      "=r"(afr[mt][2]), "=r"(afr[mt][3]) : "r"(addr));
            }
            uint32_t bfr[4][2];
            #pragma unroll
            for (int p = 0; p < 2; p++) {
                int r = kk * 16 + (lane & 15);
                int c = wn * 32 + p * 16 + (lane >> 4) * 8;
                uint32_t addr = smem_u32(&Bs[cur][r][c]);
                uint32_t r0, r1, r2, r3;
                asm volatile(
                    "ldmatrix.sync.aligned.m8n8.x4.trans.shared.b16 {%0,%1,%2,%3}, [%4];"
                    : "=r"(r0), "=r"(r1), "=r"(r2), "=r"(r3) : "r"(addr));
                bfr[p * 2][0] = r0;     bfr[p * 2][1] = r1;
                bfr[p * 2 + 1][0] = r2; bfr[p * 2 + 1][1] = r3;
            }
            #pragma unroll
            for (int mt = 0; mt < 2; mt++)
                #pragma unroll
                for (int nt = 0; nt < 4; nt++) {
                    asm volatile(
                        "mma.sync.aligned.m16n8k16.row.col.f32.f16.f16.f32 "
                        "{%0,%1,%2,%3}, {%4,%5,%6,%7}, {%8,%9}, {%0,%1,%2,%3};"
                        : "+f"(acc[mt][nt][0]), "+f"(acc[mt][nt][1]),
                          "+f"(acc[mt][nt][2]), "+f"(acc[mt][nt][3])
                        : "r"(afr[mt][0]), "r"(afr[mt][1]),
                          "r"(afr[mt][2]), "r"(afr[mt][3]),
                          "r"(bfr[nt][0]), "r"(bfr[nt][1]));
                }
        }
        __syncthreads();
    }
    #undef LOAD_STAGE

    int g = lane >> 2, t4 = lane & 3;
    float sp[2][2] = {}, tp[2][2] = {};
    #pragma unroll
    for (int mt = 0; mt < 2; mt++)
        #pragma unroll
        for (int nt = 0; nt < 4; nt++) {
            int cl = wn * 32 + nt * 8 + t4 * 2;
            int r  = row0 + wm * 32 + mt * 16;
            int c  = col0 + cl;
            __half2 lo = __floats2half2_rn(acc[mt][nt][0], acc[mt][nt][1]);
            __half2 hi = __floats2half2_rn(acc[mt][nt][2], acc[mt][nt][3]);
            *(__half2*)&C[(size_t)(r + g)     * Kout + c] = lo;
            *(__half2*)&C[(size_t)(r + g + 8) * Kout + c] = hi;
            float s0 = a_s[cl], s1 = a_s[cl + 1];
            float d0 = a_d[cl], d1 = a_d[cl + 1];
            sp[mt][0] += acc[mt][nt][0] * s0 + acc[mt][nt][1] * s1;
            sp[mt][1] += acc[mt][nt][2] * s0 + acc[mt][nt][3] * s1;
            tp[mt][0] += acc[mt][nt][0] * d0 + acc[mt][nt][1] * d1;
            tp[mt][1] += acc[mt][nt][2] * d0 + acc[mt][nt][3] * d1;
        }
    #pragma unroll
    for (int o = 1; o <= 2; o <<= 1)
        #pragma unroll
        for (int mt = 0; mt < 2; mt++) {
            sp[mt][0] += __shfl_xor_sync(0xffffffffu, sp[mt][0], o);
            sp[mt][1] += __shfl_xor_sync(0xffffffffu, sp[mt][1], o);
            tp[mt][0] += __shfl_xor_sync(0xffffffffu, tp[mt][0], o);
            tp[mt][1] += __shfl_xor_sync(0xffffffffu, tp[mt][1], o);
        }
    if (t4 == 0)
        #pragma unroll
        for (int mt = 0; mt < 2; mt++) {
            int r = wm * 32 + mt * 16 + g;
            s_sm[wn][r]     = sp[mt][0];  s_sm[wn][r + 8] = sp[mt][1];
            t_sm[wn][r]     = tp[mt][0];  t_sm[wn][r + 8] = tp[mt][1];
        }
    __syncthreads();
    if (tid < BM) {
        int r = row0 + tid;
        if (D == 64) {
            int h0 = col0 >> 6;                 // 0 or 2
            st[r * 8 + h0]         = s_sm[0][tid] + s_sm[1][tid];
            st[r * 8 + h0 + 1]     = s_sm[2][tid] + s_sm[3][tid];
            st[r * 8 + 4 + h0]     = t_sm[0][tid] + t_sm[1][tid];
            st[r * 8 + 4 + h0 + 1] = t_sm[2][tid] + t_sm[3][tid];
        } else {
            int h = col0 >> 7;                  // 0..3
            st[r * 8 + h]     = s_sm[0][tid] + s_sm[1][tid] + s_sm[2][tid] + s_sm[3][tid];
            st[r * 8 + 4 + h] = t_sm[0][tid] + t_sm[1][tid] + t_sm[2][tid] + t_sm[3][tid];
        }
    }
}

// ---------------------------------------------------------------------------
// Sparse softmax + aggregation. float4 score gathers via interleaved st.
// ---------------------------------------------------------------------------
__global__ __launch_bounds__(256) void agg_kernel(
    const __half* __restrict__ WhH, const float* __restrict__ st,
    void* __restrict__ outp, int D, int meanMode)
{
    int K   = HEADS * D;
    int CPS = K >> 3;
    int G   = 256 / CPS;
    __shared__ int   sidx[PAD];
    __shared__ float sw[HEADS][PAD];
    __shared__ float sz[HEADS];
    __shared__ float4 ssrc4;
    __shared__ float buf[2048];

    int i   = blockIdx.x;
    int tid = threadIdx.x;
    int sl  = tid % CPS;
    int g   = tid / CPS;
    int c8  = sl * 8;
    int h   = c8 / D;

    if (tid == 0) ssrc4 = *(const float4*)&st[(size_t)i * 8];
    int cnt = g_cnt[i];
    if (tid < cnt) sidx[tid] = g_col_idx[i * PAD + tid];
    __syncthreads();

    if (tid < cnt) {
        int j = sidx[tid];
        float4 tv = *(const float4*)&st[(size_t)j * 8 + 4];
        float z0 = ssrc4.x + tv.x, z1 = ssrc4.y + tv.y;
        float z2 = ssrc4.z + tv.z, z3 = ssrc4.w + tv.w;
        sw[0][tid] = (z0 > 0.f) ? z0 : 0.2f * z0;
        sw[1][tid] = (z1 > 0.f) ? z1 : 0.2f * z1;
        sw[2][tid] = (z2 > 0.f) ? z2 : 0.2f * z2;
        sw[3][tid] = (z3 > 0.f) ? z3 : 0.2f * z3;
    }
    __syncthreads();

    {
        int wid = tid >> 5, lane = tid & 31;
        if (wid < HEADS) {
            int hh = wid;
            float mx = -CUDART_INF_F;
            for (int k = lane; k < cnt; k += 32) mx = fmaxf(mx, sw[hh][k]);
            #pragma unroll
            for (int o = 16; o; o >>= 1)
                mx = fmaxf(mx, __shfl_xor_sync(0xffffffffu, mx, o));
            float lz = 0.f;
            for (int k = lane; k < cnt; k += 32) {
                float w = __expf(sw[hh][k] - mx);
                sw[hh][k] = w;
                lz += w;
            }
            #pragma unroll
            for (int o = 16; o; o >>= 1) lz += __shfl_xor_sync(0xffffffffu, lz, o);
            if (lane == 0) sz[hh] = lz;
        }
    }
    __syncthreads();

    float acc[8] = {};
    const float* swh = sw[h];
    #pragma unroll 2
    for (int k = g; k < cnt; k += G) {
        float w = swh[k];
        uint4 v = *(const uint4*)&WhH[(size_t)sidx[k] * K + c8];
        float2 p0 = __half22float2(*(__half2*)&v.x);
        float2 p1 = __half22float2(*(__half2*)&v.y);
        float2 p2 = __half22float2(*(__half2*)&v.z);
        float2 p3 = __half22float2(*(__half2*)&v.w);
        acc[0] += w * p0.x; acc[1] += w * p0.y;
        acc[2] += w * p1.x; acc[3] += w * p1.y;
        acc[4] += w * p2.x; acc[5] += w * p2.y;
        acc[6] += w * p3.x; acc[7] += w * p3.y;
    }
    float* bg = buf + g * K + c8;
    #pragma unroll
    for (int q = 0; q < 8; q++) bg[q] = acc[q];
    __syncthreads();

    if (!meanMode) {
        __half* out = (__half*)outp;
        int c = tid;
        float v = 0.f;
        for (int gg = 0; gg < G; gg++) v += buf[gg * K + c];
        v /= sz[c / D];
        v = (v > 0.f) ? v : (__expf(v) - 1.f);
        out[(size_t)i * K + c] = __float2half(v);
    } else {
        float* out = (float*)outp;
        if (tid < D) {
            float v = 0.f;
            #pragma unroll
            for (int hh = 0; hh < HEADS; hh++) {
                float hv = 0.f;
                for (int gg = 0; gg < G; gg++) hv += buf[gg * K + hh * D + tid];
                v += hv / sz[hh];
            }
            out[(size_t)i * D + tid] = 0.25f * v;
        }
    }
}

// ---------------------------------------------------------------------------
extern "C" void kernel_launch(void* const* d_in, const int* in_sizes, int n_in,
                              void* d_out, int out_size)
{
    const float* x   = (const float*)d_in[0];
    const void*  adj =               d_in[1];
    const float* W0  = (const float*)d_in[2];
    const float* a0s = (const float*)d_in[3];
    const float* a0d = (const float*)d_in[4];
    const float* W1  = (const float*)d_in[5];
    const float* a1s = (const float*)d_in[6];
    const float* a1d = (const float*)d_in[7];
    const float* W2  = (const float*)d_in[8];
    const float* a2s = (const float*)d_in[9];
    const float* a2d = (const float*)d_in[10];
    float* out = (float*)d_out;

    __half *pxh, *pW0, *pW1, *pW2, *pWhH, *phH;
    float  *pst;
    cudaGetSymbolAddress((void**)&pxh,  g_xh);
    cudaGetSymbolAddress((void**)&pW0,  g_W0h);
    cudaGetSymbolAddress((void**)&pW1,  g_W1h);
    cudaGetSymbolAddress((void**)&pW2,  g_W2h);
    cudaGetSymbolAddress((void**)&pWhH, g_WhH);
    cudaGetSymbolAddress((void**)&phH,  g_hH);
    cudaGetSymbolAddress((void**)&pst,  g_st);

    static cudaStream_t sB = 0;
    static cudaEvent_t  eFork = 0, eJoin = 0;
    if (!sB) {
        cudaStreamCreateWithFlags(&sB, cudaStreamNonBlocking);
        cudaEventCreateWithFlags(&eFork, cudaEventDisableTiming);
        cudaEventCreateWithFlags(&eJoin, cudaEventDisableTiming);
    }

    cudaEventRecord(eFork, 0);
    cudaStreamWaitEvent(sB, eFork, 0);

    prep<<<2048, 256, 0, sB>>>(x, W0, W1, W2, pxh, pW0, pW1, pW2);
    gemm_fused<<<dim3(2, GN / BM), 256, 0, sB>>>(pxh, pW0, pWhH, a0s, a0d,
                                                 pst, 256, 256, 64);
    cudaEventRecord(eJoin, sB);

    detect_kernel<<<1, 256>>>((const unsigned char*)adj);
    csr_build<<<GN / 8, 256>>>(adj);
    cudaStreamWaitEvent(0, eJoin, 0);

    agg_kernel<<<GN, 256>>>(pWhH, pst, phH, 64, 0);

    gemm_fused<<<dim3(2, GN / BM), 256>>>(phH, pW1, pWhH, a1s, a1d,
                                          pst, 256, 256, 64);
    agg_kernel<<<GN, 256>>>(pWhH, pst, phH, 64, 0);

    gemm_fused<<<dim3(4, GN / BM), 256>>>(phH, pW2, pWhH, a2s, a2d,
                                          pst, 256, 512, 128);
    agg_kernel<<<GN, 256>>>(pWhH, pst, out, 128, 1);
}